// round 4
// baseline (speedup 1.0000x reference)
#include <cuda_runtime.h>

#define NLNK 64
#define NB   16
#define NP   20
#define T    512
#define PAD  128
#define NT   128
#define DTC  0.01f
#define NOISEC 0.001f
#define LN2C 0.69314718055994530942f

typedef unsigned long long u64;

__device__ float g_partial[NB * NLNK];

union F4 {
    float4 v;
    float  f[4];
    u64    d[2];
};

__device__ __forceinline__ u64 pk(float lo, float hi) {
    u64 r;
    asm("mov.b64 %0, {%1,%2};" : "=l"(r) : "f"(lo), "f"(hi));
    return r;
}
__device__ __forceinline__ void fma2(u64& acc, u64 a, u64 b) {
    asm("fma.rn.f32x2 %0, %1, %2, %0;" : "+l"(acc) : "l"(a), "l"(b));
}
__device__ __forceinline__ u64 mul2(u64 a, u64 b) {
    u64 r;
    asm("mul.rn.f32x2 %0, %1, %2;" : "=l"(r) : "l"(a), "l"(b));
    return r;
}

__global__ void __launch_bounds__(NT) outage_kernel(const float* __restrict__ pathloss,
                                                    const float* __restrict__ powers) {
    __shared__ __align__(16) float Qbuf[2][PAD + T];
    __shared__ __align__(16) float kd[2 * T];       // duplicated taps: kd[2m]=kd[2m+1]=k[m]
    __shared__ float p2[T], p2m1[T];
    __shared__ float s_arr[NP];
    __shared__ float out20[NP];
    __shared__ float red[64];
    __shared__ float sc_diag, sc_rs;

    const int c    = blockIdx.x;
    const int b    = c >> 6;
    const int l    = c & 63;
    const int tid  = threadIdx.x;
    const int warp = tid >> 5;
    const int lane = tid & 31;

    if (tid < 64) red[tid] = pathloss[l * 64 + tid];

    for (int t = tid; t < T; t += NT) {
        float v = exp2f((float)t * DTC);
        p2[t]   = v;
        p2m1[t] = v - 1.0f;
    }
    for (int i = tid; i < PAD; i += NT) { Qbuf[0][i] = 0.0f; Qbuf[1][i] = 0.0f; }
    __syncthreads();

    if (tid == 0) {
        float rs = 0.0f;
        for (int j = 0; j < 64; j++) rs += red[j];
        sc_rs   = rs;
        sc_diag = pathloss[l * 64 + l];
    }
    __syncthreads();

    if (tid < NP) {
        float p    = powers[(b * NP + tid) * NLNK + l];
        float diag = sc_diag;
        s_arr[tid] = diag * p / (p * (sc_rs - diag) + NOISEC);
    }
    __syncthreads();

    // Q^(0)[t] = 1 - exp(-(2^t-1)*s0)
    {
        float s0 = s_arr[0];
        for (int t = tid; t < T; t += NT)
            Qbuf[0][PAD + t] = 1.0f - __expf(-p2m1[t] * s0);
    }
    __syncthreads();
    if (tid == 0) out20[0] = Qbuf[0][PAD + T - 1];

    // Warp -> t-range assignment, rotated per block for SMSP load balance
    const int trange = (warp + blockIdx.x) & 3;
    const int t0     = 4 * (trange * 32 + lane);   // 4 contiguous outputs per thread
    const int G      = 32 * (trange + 1);          // m-groups needed (triangular bound)

    int cur = 0;
    for (int n = 1; n < NP; n++) {
        // build reversed duplicated kernel: k[m] = exp(-(2^u-1)s)*2^u*s*ln2, u=T-1-m
        float s  = s_arr[n];
        float sl = s * LN2C;
        for (int m = tid; m < T; m += NT) {
            int u = T - 1 - m;
            float kv = __expf(-p2m1[u] * s) * p2[u] * sl;
            ((u64*)kd)[m] = pk(kv, kv);
        }
        __syncthreads();

        const u64*   Kd = (const u64*)kd;
        const float* Qc = &Qbuf[cur][PAD];

        u64 accA = 0ull, accB = 0ull;   // (0.f,0.f) bit pattern
        F4 a; a.v = *(const float4*)(Qc + t0);            // Q[t0 .. t0+3]
        const float4* qp = (const float4*)(Qc + t0 - 4);  // next-lower quad

        #pragma unroll 4
        for (int g = 0; g < G; g++) {
            F4 bq; bq.v = *qp; qp--;                      // Q[t0-4g-4 .. t0-4g-1]
            u64 kxx = Kd[4 * g + 0];
            u64 kyy = Kd[4 * g + 1];
            u64 kzz = Kd[4 * g + 2];
            u64 kww = Kd[4 * g + 3];
            u64 p1 = pk(bq.f[3], a.f[0]);                 // (Q[t0-1-4g], Q[t0-4g])
            u64 p2m = pk(a.f[1], a.f[2]);
            u64 p3 = pk(bq.f[1], bq.f[2]);
            // m = 4g   (kx): outputs (0,1) read (a.x,a.y); (2,3) read (a.z,a.w)
            fma2(accA, a.d[0],  kxx); fma2(accB, a.d[1], kxx);
            // m = 4g+1 (ky)
            fma2(accA, p1,      kyy); fma2(accB, p2m,    kyy);
            // m = 4g+2 (kz)
            fma2(accA, bq.d[1], kzz); fma2(accB, a.d[0], kzz);
            // m = 4g+3 (kw)
            fma2(accA, p3,      kww); fma2(accB, p1,     kww);
            a = bq;
        }

        u64 dt2 = pk(DTC, DTC);
        F4 outq;
        outq.d[0] = mul2(accA, dt2);
        outq.d[1] = mul2(accB, dt2);
        *(float4*)(&Qbuf[cur ^ 1][PAD + t0]) = outq.v;
        if (t0 == T - 4) out20[n] = outq.f[3];            // Q^(n)[511]
        __syncthreads();
        cur ^= 1;
    }

    if (tid == 0) {
        float contrib = powers[(b * NP) * NLNK + l] + 1.0f;
        #pragma unroll
        for (int n = 0; n < NP - 1; n++)
            contrib += (powers[(b * NP + n + 1) * NLNK + l] + 1.0f) * out20[n];
        contrib += out20[NP - 1];
        g_partial[c] = contrib;
    }
}

__global__ void reduce_kernel(float* __restrict__ out) {
    __shared__ float sh[256];
    int tid = threadIdx.x;
    sh[tid] = g_partial[tid] + g_partial[tid + 256] + g_partial[tid + 512] + g_partial[tid + 768];
    __syncthreads();
    for (int s = 128; s > 0; s >>= 1) {
        if (tid < s) sh[tid] += sh[tid + s];
        __syncthreads();
    }
    if (tid == 0) out[0] = sh[0];
}

extern "C" void kernel_launch(void* const* d_in, const int* in_sizes, int n_in,
                              void* d_out, int out_size) {
    const float* a0 = (const float*)d_in[0];
    const float* a1 = (const float*)d_in[1];
    const float* pathloss = a0;
    const float* powers   = a1;
    if (n_in >= 2 && in_sizes[0] != NLNK * NLNK) { pathloss = a1; powers = a0; }
    outage_kernel<<<NB * NLNK, NT>>>(pathloss, powers);
    reduce_kernel<<<1, 256>>>((float*)d_out);
}